// round 9
// baseline (speedup 1.0000x reference)
#include <cuda_runtime.h>
#include <cuda_bf16.h>
#include <cstdint>

// ---------------------------------------------------------------------------
// ROIAlignPooler (3D, 4-level FPN) for B200 (sm_100a)
//
//   1. Fused transpose: all 4 levels NCDHW -> N DHW C (channel-last scratch).
//   2. Main kernel: one block per ROI (256 blocks, 768 thr, 2 blocks/SM).
//      Per-ROI tables: merged per-dim taps; y*x fused into 49 flat
//      (byte-offset, wy*wx) lists + sentinel; z-table fused float2, padded.
//      Warp pairs cells (oz=2k, rem) and (oz=2k+1, rem): both halves share
//      the SAME yx list -> zero divergence on the hot loop.
//      Inner loop software-pipelined (next entry LDS overlaps LDG/FMA).
//   3. Output staged in shared [64][343], flat float4 coalesced writeout.
// ---------------------------------------------------------------------------

#define NROI    256
#define C_CH    64
#define CELLS   343
#define OUT_PER_ROI (C_CH * CELLS)   // 21952

__device__ __align__(16) float g_t0[2 * 40 * 40 * 40 * C_CH];
__device__ __align__(16) float g_t1[2 * 20 * 20 * 20 * C_CH];
__device__ __align__(16) float g_t2[2 * 10 * 10 * 10 * C_CH];
__device__ __align__(16) float g_t3[2 * 5 * 5 * 5 * C_CH];

// ---------------------------------------------------------------------------
// Fused transpose: src[b][c][sp] -> dst[b][sp][c], all levels in one launch.
// ---------------------------------------------------------------------------
__global__ __launch_bounds__(1024)
void transpose_all_kernel(const float* __restrict__ x0,
                          const float* __restrict__ x1,
                          const float* __restrict__ x2,
                          const float* __restrict__ x3) {
    __shared__ float tile[32][133];

    const int bx = blockIdx.x;
    const float* src; float* dst; int DHW, spTiles, t0;
    if (bx < 2000)      { src = x0; dst = g_t0; DHW = 64000; spTiles = 500; t0 = bx; }
    else if (bx < 2252) { src = x1; dst = g_t1; DHW = 8000;  spTiles = 63;  t0 = bx - 2000; }
    else if (bx < 2284) { src = x2; dst = g_t2; DHW = 1000;  spTiles = 8;   t0 = bx - 2252; }
    else                { src = x3; dst = g_t3; DHW = 125;   spTiles = 1;   t0 = bx - 2284; }

    const int st = t0 % spTiles;
    const int t1 = t0 / spTiles;
    const int cg = t1 & 1;
    const int b  = t1 >> 1;
    const int cBase = cg * 32;
    const int sBase = st * 128;
    const int tx = threadIdx.x, ty = threadIdx.y;

    if ((DHW & 3) == 0) {
        int sp4 = sBase + 4 * tx;
        if (sp4 < DHW) {
            const float4 v = *(const float4*)(
                src + (size_t)(b * C_CH + cBase + ty) * DHW + sp4);
            tile[ty][4 * tx + 0] = v.x;
            tile[ty][4 * tx + 1] = v.y;
            tile[ty][4 * tx + 2] = v.z;
            tile[ty][4 * tx + 3] = v.w;
        }
    } else {
#pragma unroll
        for (int k = 0; k < 4; k++) {
            int sp = sBase + 32 * k + tx;
            if (sp < DHW)
                tile[ty][32 * k + tx] =
                    src[(size_t)(b * C_CH + cBase + ty) * DHW + sp];
        }
    }
    __syncthreads();
#pragma unroll
    for (int k = 0; k < 4; k++) {
        int sp = sBase + 32 * k + ty;
        if (sp < DHW)
            dst[((size_t)b * DHW + sp) * C_CH + cBase + tx] = tile[tx][32 * k + ty];
    }
}

// ---------------------------------------------------------------------------
__device__ __forceinline__ void dim_taps(float start, float bin, int o, int Dsz,
                                         int stride, int* to, float* tw) {
#pragma unroll
    for (int r = 0; r < 2; r++) {
        float c = start + ((float)(2 * o + r) + 0.5f) * 0.5f * bin;
        float valid = (c > -1.0f && c < (float)Dsz) ? 0.5f : 0.0f;
        c = fminf(fmaxf(c, 0.0f), (float)Dsz - 1.0f);
        float low = floorf(c);
        int li = (int)low;
        int hi = min(li + 1, Dsz - 1);
        float f = c - low;
        to[2 * r]     = li * stride;
        tw[2 * r]     = (1.0f - f) * valid;
        to[2 * r + 1] = hi * stride;
        tw[2 * r + 1] = f * valid;
    }
}

// ---------------------------------------------------------------------------
// Main kernel: one block per ROI, 768 threads = 24 warps, 2 blocks/SM.
// ---------------------------------------------------------------------------
extern __shared__ float s_out[];   // [C_CH][CELLS] = 87808 bytes (dynamic)

__global__ __launch_bounds__(768, 2)
void roi_align_kernel(const float* __restrict__ boxes, float* __restrict__ out) {
    __shared__ int    s_cnt[3][7];
    __shared__ int    s_off[3][7][4];              // BYTE offsets
    __shared__ float  s_wt [3][7][4];
    __shared__ __align__(8) float2 s_z[7][4];      // fused z-table, zero-padded
    __shared__ int    s_nyx[49];
    __shared__ __align__(16) float2 s_yx[49][17];  // (byte-off bits, wy*wx) + sentinel

    const int r = blockIdx.x;
    const int b = r >> 7;            // nb = 128

    const float bz1 = boxes[r * 6 + 0];
    const float by1 = boxes[r * 6 + 1];
    const float bx1 = boxes[r * 6 + 2];
    const float bz2 = boxes[r * 6 + 3];
    const float by2 = boxes[r * 6 + 4];
    const float bx2 = boxes[r * 6 + 5];

    const float area = (bz2 - bz1 + 1.0f) * (by2 - by1 + 1.0f) * (bx2 - bx1 + 1.0f);
    const float s    = sqrtf(area);
    float lf = floorf(4.0f + log2f(s / 224.0f + 1e-6f));
    lf = fminf(fmaxf(lf, 2.0f), 5.0f);
    const int lvl = (int)lf - 2;

    const float* ft; int Dsz; float scale;
    if (lvl == 0)      { ft = g_t0; Dsz = 40; scale = 0.25f;    }
    else if (lvl == 1) { ft = g_t1; Dsz = 20; scale = 0.125f;   }
    else if (lvl == 2) { ft = g_t2; Dsz = 10; scale = 0.0625f;  }
    else               { ft = g_t3; Dsz = 5;  scale = 0.03125f; }

    const int DHW     = Dsz * Dsz * Dsz;
    const int strideZ = Dsz * Dsz * C_CH;
    const int strideY = Dsz * C_CH;

    const float z1 = bz1 * scale, y1 = by1 * scale, x1 = bx1 * scale;
    const float binz = fmaxf(bz2 * scale - z1, 1.0f) * (1.0f / 7.0f);
    const float biny = fmaxf(by2 * scale - y1, 1.0f) * (1.0f / 7.0f);
    const float binx = fmaxf(bx2 * scale - x1, 1.0f) * (1.0f / 7.0f);

    const int tid = threadIdx.x;

    // ---- phase 1: per-dim merged tap tables (21 threads) ----
    if (tid < 21) {
        const int dim = tid / 7;
        const int o   = tid - dim * 7;
        const float start  = (dim == 0) ? z1 : (dim == 1) ? y1 : x1;
        const float bin    = (dim == 0) ? binz : (dim == 1) ? biny : binx;
        const int   stride = (dim == 0) ? strideZ : (dim == 1) ? strideY : C_CH;

        int to[4]; float tw[4];
        dim_taps(start, bin, o, Dsz, stride, to, tw);

        int n = 0; int uo[4]; float uw[4];
#pragma unroll
        for (int t = 0; t < 4; t++) {
            if (tw[t] != 0.0f) {
                bool found = false;
#pragma unroll
                for (int j = 0; j < 4; j++) {
                    if (j < n && uo[j] == to[t]) { uw[j] += tw[t]; found = true; }
                }
                if (!found) { uo[n] = to[t]; uw[n] = tw[t]; n++; }
            }
        }
        s_cnt[dim][o] = n;
        if (dim == 0) {
            // fused, zero-padded z-table (safe to read all 4 entries)
#pragma unroll
            for (int j = 0; j < 4; j++) {
                s_z[o][j] = (j < n)
                    ? make_float2(__int_as_float(uo[j] * 4), uw[j])
                    : make_float2(__int_as_float(0), 0.0f);
            }
        } else {
#pragma unroll
            for (int j = 0; j < 4; j++) {
                if (j < n) {
                    s_off[dim][o][j] = uo[j] * 4;    // BYTE offset
                    s_wt [dim][o][j] = uw[j];
                }
            }
        }
    }
    __syncthreads();

    // ---- phase 2: fuse y*x into flat byte-offset lists + sentinel ----
    if (tid < 49) {
        const int oy = tid / 7;
        const int ox = tid - oy * 7;
        const int ny = s_cnt[1][oy];
        const int nx = s_cnt[2][ox];
        int m = 0;
        for (int j = 0; j < ny; j++) {
            const int   yo = s_off[1][oy][j];
            const float wy = s_wt[1][oy][j];
            for (int k = 0; k < nx; k++) {
                s_yx[tid][m] = make_float2(
                    __int_as_float(yo + s_off[2][ox][k]),
                    wy * s_wt[2][ox][k]);
                m++;
            }
        }
        s_yx[tid][m] = make_float2(__int_as_float(0), 0.0f);  // sentinel
        s_nyx[tid] = m;
    }
    __syncthreads();

    const int lane = tid & 31;
    const int warp = tid >> 5;       // 0..23
    const int h = lane >> 4;         // z-parity half (0/1)
    const int q = lane & 15;         // channel quad

    const char* base = (const char*)(ft + (size_t)b * DHW * C_CH + 4 * q);

    // Work items: (k, rem), k = 0..3, rem = 0..48. Half h handles oz = 2k+h.
    // Both halves share the SAME yx list (same rem) -> no inner divergence.
    for (int idx = warp; idx < 196; idx += 24) {
        const int k   = idx / 49;
        const int rem = idx - k * 49;
        const int oz  = 2 * k + h;           // 0..7
        const bool valid = (oz < 7);
        const int ozc = valid ? oz : 6;

        const int nz  = s_cnt[0][ozc];
        const int nzm = max(nz, __shfl_xor_sync(0xffffffffu, nz, 16));
        const int m   = s_nyx[rem];
        const float2* lst = s_yx[rem];

        float a0 = 0.f, a1 = 0.f, a2 = 0.f, a3 = 0.f;
        for (int i = 0; i < nzm; i++) {
            const float2 ze = s_z[ozc][i];       // (byte off, wz); 0-weight pad
            const float  wz = ze.y;
            const char*  bz = base + __float_as_int(ze.x);
            float2 e = lst[0];
            for (int t = 0; t < m; t++) {
                const float2 en = lst[t + 1];    // sentinel-safe
                const float  w  = wz * e.y;
                const float4 v  = *(const float4*)(bz + __float_as_int(e.x));
                a0 = fmaf(w, v.x, a0);
                a1 = fmaf(w, v.y, a1);
                a2 = fmaf(w, v.z, a2);
                a3 = fmaf(w, v.w, a3);
                e = en;
            }
        }

        if (valid) {
            const int cell = ozc * 49 + rem;
            s_out[(4 * q + 0) * CELLS + cell] = a0;
            s_out[(4 * q + 1) * CELLS + cell] = a1;
            s_out[(4 * q + 2) * CELLS + cell] = a2;
            s_out[(4 * q + 3) * CELLS + cell] = a3;
        }
    }

    __syncthreads();

    float4*       o4 = (float4*)(out + (size_t)r * OUT_PER_ROI);
    const float4* s4 = (const float4*)s_out;
    for (int i = tid; i < OUT_PER_ROI / 4; i += 768)
        o4[i] = s4[i];
}

// ---------------------------------------------------------------------------
extern "C" void kernel_launch(void* const* d_in, const int* in_sizes, int n_in,
                              void* d_out, int out_size) {
    const float* x0    = (const float*)d_in[0];
    const float* x1    = (const float*)d_in[1];
    const float* x2    = (const float*)d_in[2];
    const float* x3    = (const float*)d_in[3];
    const float* boxes = (const float*)d_in[4];

    cudaFuncSetAttribute(roi_align_kernel,
                         cudaFuncAttributeMaxDynamicSharedMemorySize,
                         OUT_PER_ROI * (int)sizeof(float));

    transpose_all_kernel<<<2288, dim3(32, 32)>>>(x0, x1, x2, x3);

    roi_align_kernel<<<NROI, 768, OUT_PER_ROI * (int)sizeof(float)>>>(
        boxes, (float*)d_out);
}

// round 10
// speedup vs baseline: 1.0680x; 1.0680x over previous
#include <cuda_runtime.h>
#include <cuda_bf16.h>
#include <cstdint>

// ---------------------------------------------------------------------------
// ROIAlignPooler (3D, 4-level FPN) for B200 (sm_100a)
//
//   1. Fused transpose: all 4 levels NCDHW -> N DHW C (channel-last scratch).
//   2. Main kernel: one block per ROI (256 blocks, 640 thr, 2 blocks/SM,
//      51-reg budget). Per-ROI tables: merged per-dim taps (byte offsets),
//      fused float2 z-table, y*x fused into 49 flat (byte-off, wy*wx) lists
//      + sentinel. Inner loop DOUBLE software-pipelined: next entry's LDS
//      AND next tap's LDG are issued before current tap's FMAs.
//   3. Warp: 2 cells x 16 lanes x float4 (64 ch). Output staged in shared
//      [64][343], flat float4 coalesced writeout.
// ---------------------------------------------------------------------------

#define NROI    256
#define C_CH    64
#define CELLS   343
#define OUT_PER_ROI (C_CH * CELLS)   // 21952

__device__ __align__(16) float g_t0[2 * 40 * 40 * 40 * C_CH];
__device__ __align__(16) float g_t1[2 * 20 * 20 * 20 * C_CH];
__device__ __align__(16) float g_t2[2 * 10 * 10 * 10 * C_CH];
__device__ __align__(16) float g_t3[2 * 5 * 5 * 5 * C_CH];

// ---------------------------------------------------------------------------
// Fused transpose: src[b][c][sp] -> dst[b][sp][c], all levels in one launch.
// ---------------------------------------------------------------------------
__global__ __launch_bounds__(1024)
void transpose_all_kernel(const float* __restrict__ x0,
                          const float* __restrict__ x1,
                          const float* __restrict__ x2,
                          const float* __restrict__ x3) {
    __shared__ float tile[32][133];

    const int bx = blockIdx.x;
    const float* src; float* dst; int DHW, spTiles, t0;
    if (bx < 2000)      { src = x0; dst = g_t0; DHW = 64000; spTiles = 500; t0 = bx; }
    else if (bx < 2252) { src = x1; dst = g_t1; DHW = 8000;  spTiles = 63;  t0 = bx - 2000; }
    else if (bx < 2284) { src = x2; dst = g_t2; DHW = 1000;  spTiles = 8;   t0 = bx - 2252; }
    else                { src = x3; dst = g_t3; DHW = 125;   spTiles = 1;   t0 = bx - 2284; }

    const int st = t0 % spTiles;
    const int t1 = t0 / spTiles;
    const int cg = t1 & 1;
    const int b  = t1 >> 1;
    const int cBase = cg * 32;
    const int sBase = st * 128;
    const int tx = threadIdx.x, ty = threadIdx.y;

    if ((DHW & 3) == 0) {
        int sp4 = sBase + 4 * tx;
        if (sp4 < DHW) {
            const float4 v = *(const float4*)(
                src + (size_t)(b * C_CH + cBase + ty) * DHW + sp4);
            tile[ty][4 * tx + 0] = v.x;
            tile[ty][4 * tx + 1] = v.y;
            tile[ty][4 * tx + 2] = v.z;
            tile[ty][4 * tx + 3] = v.w;
        }
    } else {
#pragma unroll
        for (int k = 0; k < 4; k++) {
            int sp = sBase + 32 * k + tx;
            if (sp < DHW)
                tile[ty][32 * k + tx] =
                    src[(size_t)(b * C_CH + cBase + ty) * DHW + sp];
        }
    }
    __syncthreads();
#pragma unroll
    for (int k = 0; k < 4; k++) {
        int sp = sBase + 32 * k + ty;
        if (sp < DHW)
            dst[((size_t)b * DHW + sp) * C_CH + cBase + tx] = tile[tx][32 * k + ty];
    }
}

// ---------------------------------------------------------------------------
__device__ __forceinline__ void dim_taps(float start, float bin, int o, int Dsz,
                                         int stride, int* to, float* tw) {
#pragma unroll
    for (int r = 0; r < 2; r++) {
        float c = start + ((float)(2 * o + r) + 0.5f) * 0.5f * bin;
        float valid = (c > -1.0f && c < (float)Dsz) ? 0.5f : 0.0f;
        c = fminf(fmaxf(c, 0.0f), (float)Dsz - 1.0f);
        float low = floorf(c);
        int li = (int)low;
        int hi = min(li + 1, Dsz - 1);
        float f = c - low;
        to[2 * r]     = li * stride;
        tw[2 * r]     = (1.0f - f) * valid;
        to[2 * r + 1] = hi * stride;
        tw[2 * r + 1] = f * valid;
    }
}

// ---------------------------------------------------------------------------
// Main kernel: one block per ROI, 640 threads = 20 warps, 2 blocks/SM.
// ---------------------------------------------------------------------------
extern __shared__ float s_out[];   // [C_CH][CELLS] = 87808 bytes (dynamic)

__global__ __launch_bounds__(640, 2)
void roi_align_kernel(const float* __restrict__ boxes, float* __restrict__ out) {
    __shared__ int    s_cnt[3][7];
    __shared__ int    s_off[3][7][4];              // BYTE offsets (y/x rows)
    __shared__ float  s_wt [3][7][4];
    __shared__ __align__(8) float2 s_z[7][4];      // fused z-table (byte off, wz)
    __shared__ int    s_nyx[49];
    __shared__ __align__(16) float2 s_yx[49][17];  // (byte-off bits, wy*wx) + sentinel

    const int r = blockIdx.x;
    const int b = r >> 7;            // nb = 128

    const float bz1 = boxes[r * 6 + 0];
    const float by1 = boxes[r * 6 + 1];
    const float bx1 = boxes[r * 6 + 2];
    const float bz2 = boxes[r * 6 + 3];
    const float by2 = boxes[r * 6 + 4];
    const float bx2 = boxes[r * 6 + 5];

    const float area = (bz2 - bz1 + 1.0f) * (by2 - by1 + 1.0f) * (bx2 - bx1 + 1.0f);
    const float s    = sqrtf(area);
    float lf = floorf(4.0f + log2f(s / 224.0f + 1e-6f));
    lf = fminf(fmaxf(lf, 2.0f), 5.0f);
    const int lvl = (int)lf - 2;

    const float* ft; int Dsz; float scale;
    if (lvl == 0)      { ft = g_t0; Dsz = 40; scale = 0.25f;    }
    else if (lvl == 1) { ft = g_t1; Dsz = 20; scale = 0.125f;   }
    else if (lvl == 2) { ft = g_t2; Dsz = 10; scale = 0.0625f;  }
    else               { ft = g_t3; Dsz = 5;  scale = 0.03125f; }

    const int DHW     = Dsz * Dsz * Dsz;
    const int strideZ = Dsz * Dsz * C_CH;
    const int strideY = Dsz * C_CH;

    const float z1 = bz1 * scale, y1 = by1 * scale, x1 = bx1 * scale;
    const float binz = fmaxf(bz2 * scale - z1, 1.0f) * (1.0f / 7.0f);
    const float biny = fmaxf(by2 * scale - y1, 1.0f) * (1.0f / 7.0f);
    const float binx = fmaxf(bx2 * scale - x1, 1.0f) * (1.0f / 7.0f);

    const int tid = threadIdx.x;

    // ---- phase 1: per-dim merged tap tables (21 threads) ----
    if (tid < 21) {
        const int dim = tid / 7;
        const int o   = tid - dim * 7;
        const float start  = (dim == 0) ? z1 : (dim == 1) ? y1 : x1;
        const float bin    = (dim == 0) ? binz : (dim == 1) ? biny : binx;
        const int   stride = (dim == 0) ? strideZ : (dim == 1) ? strideY : C_CH;

        int to[4]; float tw[4];
        dim_taps(start, bin, o, Dsz, stride, to, tw);

        int n = 0; int uo[4]; float uw[4];
#pragma unroll
        for (int t = 0; t < 4; t++) {
            if (tw[t] != 0.0f) {
                bool found = false;
#pragma unroll
                for (int j = 0; j < 4; j++) {
                    if (j < n && uo[j] == to[t]) { uw[j] += tw[t]; found = true; }
                }
                if (!found) { uo[n] = to[t]; uw[n] = tw[t]; n++; }
            }
        }
        s_cnt[dim][o] = n;
        if (dim == 0) {
#pragma unroll
            for (int j = 0; j < 4; j++) {
                s_z[o][j] = (j < n)
                    ? make_float2(__int_as_float(uo[j] * 4), uw[j])
                    : make_float2(__int_as_float(0), 0.0f);
            }
        } else {
#pragma unroll
            for (int j = 0; j < 4; j++) {
                if (j < n) {
                    s_off[dim][o][j] = uo[j] * 4;    // BYTE offset
                    s_wt [dim][o][j] = uw[j];
                }
            }
        }
    }
    __syncthreads();

    // ---- phase 2: fuse y*x into flat byte-offset lists + sentinel ----
    if (tid < 49) {
        const int oy = tid / 7;
        const int ox = tid - oy * 7;
        const int ny = s_cnt[1][oy];
        const int nx = s_cnt[2][ox];
        int m = 0;
        for (int j = 0; j < ny; j++) {
            const int   yo = s_off[1][oy][j];
            const float wy = s_wt[1][oy][j];
            for (int k = 0; k < nx; k++) {
                s_yx[tid][m] = make_float2(
                    __int_as_float(yo + s_off[2][ox][k]),
                    wy * s_wt[2][ox][k]);
                m++;
            }
        }
        s_yx[tid][m] = make_float2(__int_as_float(0), 0.0f);  // sentinel (off 0, w 0)
        s_nyx[tid] = m;
    }
    __syncthreads();

    const int lane = tid & 31;
    const int warp = tid >> 5;       // 0..19
    const int h = lane >> 4;         // cell half
    const int q = lane & 15;         // channel quad

    const char* base = (const char*)(ft + (size_t)b * DHW * C_CH + 4 * q);

    for (int cb = 2 * warp; cb < CELLS; cb += 40) {
        const int cell = cb + h;
        const int cc   = min(cell, CELLS - 1);
        const int oz   = cc / 49;
        const int rem  = cc - oz * 49;

        const int nz = s_cnt[0][oz];
        const int m  = s_nyx[rem];
        const float2* lst = s_yx[rem];

        float a0 = 0.f, a1 = 0.f, a2 = 0.f, a3 = 0.f;
        for (int i = 0; i < nz; i++) {
            const float2 ze = s_z[oz][i];
            const float  wz = ze.y;
            const char*  bz = base + __float_as_int(ze.x);

            // double software pipeline: entry + value prefetch
            float2 e = lst[0];
            float4 v = *(const float4*)(bz + __float_as_int(e.x));
            for (int t = 0; t < m; t++) {
                const float2 en = lst[t + 1];                        // sentinel-safe
                const float4 vn = *(const float4*)(bz + __float_as_int(en.x));
                const float  w  = wz * e.y;
                a0 = fmaf(w, v.x, a0);
                a1 = fmaf(w, v.y, a1);
                a2 = fmaf(w, v.z, a2);
                a3 = fmaf(w, v.w, a3);
                e = en; v = vn;
            }
        }

        if (cell < CELLS) {
            s_out[(4 * q + 0) * CELLS + cell] = a0;
            s_out[(4 * q + 1) * CELLS + cell] = a1;
            s_out[(4 * q + 2) * CELLS + cell] = a2;
            s_out[(4 * q + 3) * CELLS + cell] = a3;
        }
    }

    __syncthreads();

    float4*       o4 = (float4*)(out + (size_t)r * OUT_PER_ROI);
    const float4* s4 = (const float4*)s_out;
    for (int i = tid; i < OUT_PER_ROI / 4; i += 640)
        o4[i] = s4[i];
}

// ---------------------------------------------------------------------------
extern "C" void kernel_launch(void* const* d_in, const int* in_sizes, int n_in,
                              void* d_out, int out_size) {
    const float* x0    = (const float*)d_in[0];
    const float* x1    = (const float*)d_in[1];
    const float* x2    = (const float*)d_in[2];
    const float* x3    = (const float*)d_in[3];
    const float* boxes = (const float*)d_in[4];

    cudaFuncSetAttribute(roi_align_kernel,
                         cudaFuncAttributeMaxDynamicSharedMemorySize,
                         OUT_PER_ROI * (int)sizeof(float));

    transpose_all_kernel<<<2288, dim3(32, 32)>>>(x0, x1, x2, x3);

    roi_align_kernel<<<NROI, 640, OUT_PER_ROI * (int)sizeof(float)>>>(
        boxes, (float*)d_out);
}